// round 11
// baseline (speedup 1.0000x reference)
#include <cuda_runtime.h>
#include <cuda_bf16.h>
#include <cstdint>

#define B_ 128
#define T_ 500
#define D_ 700
#define H_ 512
#define O_ 20
#define K1 704       // GEMM1 K: D padded to 704 (11 stages of 64)
#define SBUF 16384   // one stage buffer: 128 rows x 128 B (SW128 swizzled)
#define STG 3        // cp.async pipeline depth
#define GSMEM (2 * STG * SBUF)   // 98304 bytes dynamic smem
#define ERS 272      // epilogue smem row stride
#define L2SMEM (512 * 64 * 4)    // layer2 W2 slice: 512 h x 64 bf162 = 131072 B

// ---------------- scratch (static device globals: no allocation allowed) ----------------
__device__ __nv_bfloat16 g_xc[(size_t)T_ * B_ * K1];   // 90 MB  x as bf16 [t][b][k]
__device__ __nv_bfloat16 g_w1[(size_t)H_ * K1];        // W1 bf16 [h][k]
__device__ __nv_bfloat16 g_w2t[(size_t)H_ * H_];       // W2^T bf16 [h][g]
__device__ __nv_bfloat16 g_cur[(size_t)T_ * B_ * H_];  // 65 MB  cur1 [t][b][h]
__device__ uint8_t       g_seg[(size_t)B_ * T_ * 512]; // per-warp spike segments (u8 lane)
__device__ uint8_t       g_scnt[(size_t)B_ * T_ * 16]; // per-warp spike counts
__device__ uint32_t      g_cnt[B_ * T_];               // total spikes per (b,t)
__device__ uint16_t      g_lst[(size_t)B_ * T_ * 512]; // compacted h lists per (b,t)
__device__ float         g_S2[B_ * H_];                // sum over t of s2

// ---------------- helpers ----------------
__device__ __forceinline__ uint32_t smem_u32(const void* p) {
    uint32_t a;
    asm("{ .reg .u64 t; cvta.to.shared.u64 t, %1; cvt.u32.u64 %0, t; }" : "=r"(a) : "l"(p));
    return a;
}
__device__ __forceinline__ void cp16(uint32_t s, const void* g) {
    asm volatile("cp.async.cg.shared.global [%0], [%1], 16;" :: "r"(s), "l"(g));
}
__device__ __forceinline__ void ldsm4(uint32_t& r0, uint32_t& r1, uint32_t& r2,
                                      uint32_t& r3, uint32_t addr) {
    asm volatile("ldmatrix.sync.aligned.m8n8.x4.shared.b16 {%0,%1,%2,%3}, [%4];"
                 : "=r"(r0), "=r"(r1), "=r"(r2), "=r"(r3) : "r"(addr));
}
__device__ __forceinline__ void mma16816(float* c, const uint32_t* a, const uint32_t* b) {
    asm volatile(
        "mma.sync.aligned.m16n8k16.row.col.f32.bf16.bf16.f32 "
        "{%0,%1,%2,%3}, {%4,%5,%6,%7}, {%8,%9}, {%0,%1,%2,%3};"
        : "+f"(c[0]), "+f"(c[1]), "+f"(c[2]), "+f"(c[3])
        : "r"(a[0]), "r"(a[1]), "r"(a[2]), "r"(a[3]), "r"(b[0]), "r"(b[1]));
}
__device__ __forceinline__ uint32_t sw128(uint32_t off) {   // SW128: bits[9:7] ^-> [6:4]
    return off ^ ((off >> 3) & 0x70u);
}

// ---------------- prep: fp32 -> bf16 (grid-stride over 8B output chunks) --------------
__global__ __launch_bounds__(256) void prep_x(const float* __restrict__ x) {
    const int total = B_ * T_ * 176;                   // 176 uint2-chunks per row (incl pad)
    for (int c = blockIdx.x * 256 + threadIdx.x; c < total; c += gridDim.x * 256) {
        const int bt = c / 176, i = c - bt * 176;      // x is [B][T][D]
        const int b = bt / T_, t = bt - b * T_;
        __nv_bfloat16* o = g_xc + ((size_t)t * B_ + b) * K1;
        if (i < 175) {
            float4 v = ((const float4*)(x + (size_t)bt * D_))[i];
            __nv_bfloat162 p0 = __floats2bfloat162_rn(v.x, v.y);
            __nv_bfloat162 p1 = __floats2bfloat162_rn(v.z, v.w);
            uint2 u;
            u.x = *(uint32_t*)&p0;
            u.y = *(uint32_t*)&p1;
            *(uint2*)(o + 4 * i) = u;
        } else {
            *(uint2*)(o + 700) = make_uint2(0u, 0u);   // pad 700..703
        }
    }
}
__global__ void prep_w1(const float* __restrict__ W1) {
    const int h = blockIdx.x;
    const float* wr = W1 + (size_t)h * D_;
    __nv_bfloat16* o = g_w1 + (size_t)h * K1;
    for (int d = threadIdx.x; d < D_; d += 256)
        o[d] = __float2bfloat16(wr[d]);
    if (threadIdx.x < K1 - D_) o[D_ + threadIdx.x] = __float2bfloat16(0.f);
}
__global__ void prep_w2t(const float* __restrict__ W2) {
    int i = blockIdx.x * blockDim.x + threadIdx.x;     // i = h*512 + g
    if (i < H_ * H_) {
        int h = i >> 9, g = i & 511;
        g_w2t[i] = __float2bfloat16(W2[g * H_ + h]);
    }
}

// ---------------- GEMM1: cur1[t][b][h] = bf16(xc[t,b,:].w1[h,:] + b1[h]) ----------------
// grid (4 n-tiles, 500 t), 256 threads. CTA tile M=128 x N=128, K=704 bf16.
// 8 warps as 2(m)x4(n), each 64x32 via m16n8k16. K-stage 64 (SW128), 3-stage ring.
template <int KK>
__global__ __launch_bounds__(256, 2) void gemm_mma(const __nv_bfloat16* __restrict__ Asrc,
                                                   const __nv_bfloat16* __restrict__ Bsrc,
                                                   const float* __restrict__ bias,
                                                   __nv_bfloat16* __restrict__ outp) {
    constexpr int NS = KK / 64;
    constexpr int KB2 = KK * 2;
    extern __shared__ __align__(128) char smem[];
    const int tid = threadIdx.x, lane = tid & 31, wid = tid >> 5;
    const int t = blockIdx.y, nbase = blockIdx.x * 128;
    const int wm = wid >> 2, wn = wid & 3;

    const char* gA = (const char*)Asrc + (size_t)t * B_ * KB2;
    const char* gB = (const char*)Bsrc + (size_t)nbase * KB2;
    const uint32_t sAu = smem_u32(smem);
    const uint32_t sBu = sAu + STG * SBUF;

    const int lrow = tid >> 1;
    const int lhalf = (tid & 1) * 64;
    const size_t grow = (size_t)lrow * KB2;

    const int arow = lane & 15;
    const int acol = (lane >> 4) * 16;
    const int brow = (lane & 7) + ((lane & 16) ? 8 : 0);
    const int bcol = (lane & 8) ? 16 : 0;

    float acc[4][4][4];
#pragma unroll
    for (int i = 0; i < 4; i++)
#pragma unroll
        for (int j = 0; j < 4; j++)
#pragma unroll
            for (int q = 0; q < 4; q++) acc[i][j][q] = 0.f;

#define LOADSTAGE(s, buf)                                                       \
    do {                                                                        \
        const char* ga = gA + grow + (s) * 128 + lhalf;                         \
        const char* gb = gB + grow + (s) * 128 + lhalf;                         \
        const uint32_t rb = (uint32_t)(lrow * 128 + lhalf);                     \
        _Pragma("unroll")                                                       \
        for (int j = 0; j < 4; j++) {                                           \
            uint32_t sw = sw128(rb + j * 16);                                   \
            cp16(sAu + (buf) * SBUF + sw, ga + j * 16);                         \
            cp16(sBu + (buf) * SBUF + sw, gb + j * 16);                         \
        }                                                                       \
    } while (0)

#pragma unroll
    for (int p = 0; p < STG - 1; p++) {
        LOADSTAGE(p, p);
        asm volatile("cp.async.commit_group;");
    }

    int buf = 0, nbuf = STG - 1;
    for (int s = 0; s < NS; s++) {
        asm volatile("cp.async.wait_group 1;");
        __syncthreads();
        if (s + STG - 1 < NS) LOADSTAGE(s + STG - 1, nbuf);
        asm volatile("cp.async.commit_group;");

        const uint32_t abase = sAu + buf * SBUF;
        const uint32_t bbase = sBu + buf * SBUF;
#pragma unroll
        for (int ks = 0; ks < 4; ks++) {
            uint32_t a[4][4], bf[4][2];
#pragma unroll
            for (int i = 0; i < 4; i++)
                ldsm4(a[i][0], a[i][1], a[i][2], a[i][3],
                      abase + sw128((wm * 64 + i * 16 + arow) * 128 + ks * 32 + acol));
#pragma unroll
            for (int j = 0; j < 2; j++)
                ldsm4(bf[2 * j][0], bf[2 * j][1], bf[2 * j + 1][0], bf[2 * j + 1][1],
                      bbase + sw128((wn * 32 + j * 16 + brow) * 128 + ks * 32 + bcol));
#pragma unroll
            for (int i = 0; i < 4; i++)
#pragma unroll
                for (int j = 0; j < 4; j++) mma16816(acc[i][j], a[i], bf[j]);
        }
        buf = (buf + 1 == STG) ? 0 : buf + 1;
        nbuf = (nbuf + 1 == STG) ? 0 : nbuf + 1;
    }
    __syncthreads();

    const int r0 = wm * 64 + (lane >> 2);
    const int cb = wn * 32 + (lane & 3) * 2;
#pragma unroll
    for (int j = 0; j < 4; j++) {
        const int col = nbase + cb + j * 8;
        const float2 bl = *(const float2*)(bias + col);
#pragma unroll
        for (int i = 0; i < 4; i++) {
            const int rb = r0 + i * 16;
            __nv_bfloat162 v0 = __floats2bfloat162_rn(acc[i][j][0] + bl.x,
                                                      acc[i][j][1] + bl.y);
            __nv_bfloat162 v1 = __floats2bfloat162_rn(acc[i][j][2] + bl.x,
                                                      acc[i][j][3] + bl.y);
            *(uint32_t*)(smem + rb * ERS + (cb + j * 8) * 2)       = *(uint32_t*)&v0;
            *(uint32_t*)(smem + (rb + 8) * ERS + (cb + j * 8) * 2) = *(uint32_t*)&v1;
        }
    }
    __syncthreads();
    char* gOut = (char*)outp + ((size_t)t * B_ * H_ + nbase) * 2;
#pragma unroll
    for (int c = tid; c < 2048; c += 256) {
        const int row = c >> 4, off = (c & 15) * 16;
        uint4 v = *(const uint4*)(smem + row * ERS + off);
        *(uint4*)(gOut + (size_t)row * (H_ * 2) + off) = v;
    }
}

// ---------------- scan1: LIF over cur1, emits per-warp ballot-compacted segments -------
// grid (2 h-halves, 128 b), 256 threads; thread = one (b,h). No block barriers.
__global__ __launch_bounds__(256) void scan1_seg() {
    const int half = blockIdx.x, b = blockIdx.y;
    const int tid = threadIdx.x, lane = tid & 31, w = tid >> 5;
    const int h = half * 256 + tid;
    const int wg = half * 8 + w;                       // segment 0..15
    const __nv_bfloat16* cp = g_cur + (size_t)b * H_ + h;
    uint8_t* segb = g_seg + (size_t)(b * T_) * 512 + wg * 32;
    uint8_t* scb  = g_scnt + (size_t)(b * T_) * 16 + wg;
    float v = 0.f;
    for (int t0 = 0; t0 < T_; t0 += 10) {
        float I[10];
#pragma unroll
        for (int u = 0; u < 10; u++)
            I[u] = __bfloat162float(cp[(size_t)(t0 + u) * (B_ * H_)]);
#pragma unroll
        for (int u = 0; u < 10; u++) {
            v += (I[u] - v) * 0.5f;
            bool s = (v >= 1.0f);
            unsigned m = __ballot_sync(0xffffffffu, s);
            const int t = t0 + u;
            if (s) {
                int pos = __popc(m & ((1u << lane) - 1u));
                segb[(size_t)t * 512 + pos] = (uint8_t)lane;
                v = 0.f;
            }
            if (lane == 0) scb[(size_t)t * 16] = (uint8_t)__popc(m);
        }
    }
}

// ---------------- compact: merge 16 segments -> one u16 h-list per (b,t) --------------
// warp per (b,t): 8000 blocks x 256 threads.
__global__ __launch_bounds__(256) void compact_kernel() {
    const int bt = blockIdx.x * 8 + (threadIdx.x >> 5);
    const int lane = threadIdx.x & 31;
    const uint8_t* sc = g_scnt + (size_t)bt * 16;
    unsigned c = (lane < 16) ? sc[lane] : 0u;
    unsigned pref = c;
#pragma unroll
    for (int d = 1; d < 16; d <<= 1) {
        unsigned x = __shfl_up_sync(0xffffffffu, pref, d);
        if (lane >= d) pref += x;
    }
    unsigned excl = pref - c;
    if (lane == 15) g_cnt[bt] = pref;
    const uint8_t* seg = g_seg + (size_t)bt * 512;
    uint16_t* out = g_lst + (size_t)bt * 512;
#pragma unroll
    for (int w = 0; w < 16; w++) {
        unsigned cw  = __shfl_sync(0xffffffffu, c, w);
        unsigned off = __shfl_sync(0xffffffffu, excl, w);
        if (lane < cw) out[off + lane] = (uint16_t)(w * 32 + seg[w * 32 + lane]);
    }
}

// ---------------- layer2: sparse cur2 + LIF scan2 + time-sum, fully fused --------------
// grid (4 gq, 32 bg), 256 threads = 4 b x 64 g-pairs. W2^T slice in smem (128 KB).
__global__ __launch_bounds__(256) void layer2_kernel(const float* __restrict__ b2) {
    extern __shared__ __align__(128) char smem[];
    __nv_bfloat162* Ws = (__nv_bfloat162*)smem;        // Ws[h*64 + gp]
    const int gq = blockIdx.x;
    const int tid = threadIdx.x;
    // cooperative smem load: 8192 uint4 chunks; chunk c -> h = c>>4, q = c&15
    for (int c = tid; c < 8192; c += 256) {
        const int h = c >> 4, q = c & 15;
        ((uint4*)smem)[c] =
            *(const uint4*)(g_w2t + (size_t)h * H_ + gq * 128 + q * 8);
    }
    __syncthreads();

    const int bl = tid >> 6, gp = tid & 63;
    const int b = blockIdx.y * 4 + bl;
    const int g0 = gq * 128 + 2 * gp;
    const float2 bb = make_float2(b2[g0], b2[g0 + 1]);
    const uint32_t* cntp = g_cnt + b * T_;
    const uint16_t* lstb = g_lst + (size_t)(b * T_) * 512;
    const __nv_bfloat162 z2 = __floats2bfloat162_rn(0.f, 0.f);

    float v0 = 0.f, v1 = 0.f, c0 = 0.f, c1 = 0.f;
    for (int t = 0; t < T_; t++) {
        const int cnt = cntp[t];
        const uint16_t* L = lstb + (size_t)t * 512;
        __nv_bfloat162 a0 = z2, a1 = z2;
        int i = 0;
        for (; i + 4 <= cnt; i += 4) {
            uint2 q = *(const uint2*)(L + i);          // 4 h's in one 8B load
            const int h0 = q.x & 0xffff, h1 = q.x >> 16;
            const int h2 = q.y & 0xffff, h3 = q.y >> 16;
            a0 = __hadd2(a0, Ws[h0 * 64 + gp]);
            a1 = __hadd2(a1, Ws[h1 * 64 + gp]);
            a0 = __hadd2(a0, Ws[h2 * 64 + gp]);
            a1 = __hadd2(a1, Ws[h3 * 64 + gp]);
        }
        for (; i < cnt; i++)
            a0 = __hadd2(a0, Ws[(int)L[i] * 64 + gp]);
        float2 cc = __bfloat1622float2(__hadd2(a0, a1));
        const float cur0 = cc.x + bb.x, cur1 = cc.y + bb.y;
        v0 += (cur0 - v0) * 0.5f;
        v1 += (cur1 - v1) * 0.5f;
        if (v0 >= 1.0f) { v0 = 0.f; c0 += 1.f; }
        if (v1 >= 1.0f) { v1 = 0.f; c1 += 1.f; }
    }
    *(float2*)(g_S2 + b * H_ + g0) = make_float2(c0, c1);
}

// ---------------- final: out[b,o] = 500*b3[o] + sum_h S2[b,h] * W3[o,h] ----------------
__global__ void final_kernel(const float* __restrict__ W3, const float* __restrict__ b3,
                             float* __restrict__ out) {
    __shared__ float sW3[O_ * H_];
    __shared__ float part[4 * O_];
    const int b = blockIdx.x, tid = threadIdx.x;
    for (int i = tid; i < O_ * H_; i += 128) sW3[i] = W3[i];
    __syncthreads();

    float acc[O_];
#pragma unroll
    for (int o = 0; o < O_; o++) acc[o] = 0.f;
    for (int h = tid; h < H_; h += 128) {
        float s2 = g_S2[b * H_ + h];
#pragma unroll
        for (int o = 0; o < O_; o++) acc[o] += s2 * sW3[o * H_ + h];
    }
#pragma unroll
    for (int off = 16; off; off >>= 1)
#pragma unroll
        for (int o = 0; o < O_; o++)
            acc[o] += __shfl_down_sync(0xffffffffu, acc[o], off);
    if ((tid & 31) == 0)
#pragma unroll
        for (int o = 0; o < O_; o++) part[(tid >> 5) * O_ + o] = acc[o];
    __syncthreads();
    if (tid < O_) {
        float r = 500.0f * b3[tid];
#pragma unroll
        for (int w = 0; w < 4; w++) r += part[w * O_ + tid];
        out[b * O_ + tid] = r;
    }
}

// ---------------- launch ----------------
extern "C" void kernel_launch(void* const* d_in, const int* in_sizes, int n_in,
                              void* d_out, int out_size) {
    const float* x  = (const float*)d_in[0];   // [128, 500, 700]
    const float* W1 = (const float*)d_in[1];   // [512, 700]
    const float* b1 = (const float*)d_in[2];   // [512]
    const float* W2 = (const float*)d_in[3];   // [512, 512]
    const float* b2 = (const float*)d_in[4];   // [512]
    const float* W3 = (const float*)d_in[5];   // [20, 512]
    const float* b3 = (const float*)d_in[6];   // [20]
    float* out = (float*)d_out;                // [128, 20]

    __nv_bfloat16* xc;   cudaGetSymbolAddress((void**)&xc,   g_xc);
    __nv_bfloat16* w1c;  cudaGetSymbolAddress((void**)&w1c,  g_w1);
    __nv_bfloat16* curc; cudaGetSymbolAddress((void**)&curc, g_cur);

    cudaFuncSetAttribute(gemm_mma<K1>, cudaFuncAttributeMaxDynamicSharedMemorySize, GSMEM);
    cudaFuncSetAttribute(layer2_kernel, cudaFuncAttributeMaxDynamicSharedMemorySize, L2SMEM);

    prep_x<<<8192, 256>>>(x);
    prep_w1<<<H_, 256>>>(W1);
    prep_w2t<<<(H_ * H_ + 255) / 256, 256>>>(W2);
    gemm_mma<K1><<<dim3(H_ / 128, T_), 256, GSMEM>>>(xc, w1c, b1, curc);   // cur1
    scan1_seg<<<dim3(2, B_), 256>>>();                                     // spike segments
    compact_kernel<<<B_ * T_ / 8, 256>>>();                                // u16 h-lists
    layer2_kernel<<<dim3(4, 32), 256, L2SMEM>>>(b2);                       // S2 (fused)
    final_kernel<<<B_, 128>>>(W3, b3, out);
}

// round 13
// speedup vs baseline: 2.0154x; 2.0154x over previous
#include <cuda_runtime.h>
#include <cuda_bf16.h>
#include <cstdint>

#define B_ 128
#define T_ 500
#define D_ 700
#define H_ 512
#define O_ 20
#define K1 704       // GEMM1 K: D padded to 704 (11 stages of 64)
#define K2 512       // GEMM2 K: H (8 stages of 64)
#define SBUF 16384   // one stage buffer: 128 rows x 128 B (SW128 swizzled)
#define STG 3        // cp.async pipeline depth
#define GSMEM (2 * STG * SBUF)   // 98304 bytes dynamic smem
#define ERS 272      // epilogue smem row stride
#define NCH 5        // time chunks
#define CH 100       // T per chunk

// ---------------- scratch (static device globals: no allocation allowed) ----------------
__device__ __nv_bfloat16 g_xc[(size_t)T_ * B_ * K1];   // 90 MB  x as bf16 [t][b][k]
__device__ __nv_bfloat16 g_w1[(size_t)H_ * K1];        // W1 bf16 [h][k]
__device__ __nv_bfloat16 g_w2[(size_t)H_ * K2];        // W2 bf16 [g][h]
__device__ __nv_bfloat16 g_cur[(size_t)T_ * B_ * H_];  // 65 MB  cur1 then cur2 [t][b][h]
__device__ __nv_bfloat16 g_s1[(size_t)T_ * B_ * H_];   // 65 MB  s1 dense bf16 [t][b][h]
__device__ float         g_v1[B_ * H_];                // scan1 membrane state
__device__ float         g_v2[B_ * H_];                // scan2 membrane state
__device__ float         g_S2[B_ * H_];                // running spike counts (layer 2)

// ---------------- helpers ----------------
__device__ __forceinline__ uint32_t smem_u32(const void* p) {
    uint32_t a;
    asm("{ .reg .u64 t; cvta.to.shared.u64 t, %1; cvt.u32.u64 %0, t; }" : "=r"(a) : "l"(p));
    return a;
}
__device__ __forceinline__ void cp16(uint32_t s, const void* g) {
    asm volatile("cp.async.cg.shared.global [%0], [%1], 16;" :: "r"(s), "l"(g));
}
__device__ __forceinline__ void ldsm4(uint32_t& r0, uint32_t& r1, uint32_t& r2,
                                      uint32_t& r3, uint32_t addr) {
    asm volatile("ldmatrix.sync.aligned.m8n8.x4.shared.b16 {%0,%1,%2,%3}, [%4];"
                 : "=r"(r0), "=r"(r1), "=r"(r2), "=r"(r3) : "r"(addr));
}
__device__ __forceinline__ void mma16816(float* c, const uint32_t* a, const uint32_t* b) {
    asm volatile(
        "mma.sync.aligned.m16n8k16.row.col.f32.bf16.bf16.f32 "
        "{%0,%1,%2,%3}, {%4,%5,%6,%7}, {%8,%9}, {%0,%1,%2,%3};"
        : "+f"(c[0]), "+f"(c[1]), "+f"(c[2]), "+f"(c[3])
        : "r"(a[0]), "r"(a[1]), "r"(a[2]), "r"(a[3]), "r"(b[0]), "r"(b[1]));
}
__device__ __forceinline__ uint32_t sw128(uint32_t off) {   // SW128: bits[9:7] ^-> [6:4]
    return off ^ ((off >> 3) & 0x70u);
}

// ---------------- prep: fp32 -> bf16, one time-chunk per launch ----------------
// grid 8800 x 256: exactly CH*B_*176 8B-chunks.
__global__ __launch_bounds__(256) void prep_x_chunk(const float* __restrict__ x, int t0) {
    const int c = blockIdx.x * 256 + threadIdx.x;
    const int tb = c / 176, i = c - tb * 176;
    const int tl = tb / B_, b = tb - tl * B_;
    const int t = t0 + tl;
    const float* xr = x + ((size_t)b * T_ + t) * D_;   // x is [B][T][D]
    __nv_bfloat16* o = g_xc + ((size_t)t * B_ + b) * K1;
    if (i < 175) {
        float4 v = ((const float4*)xr)[i];
        __nv_bfloat162 p0 = __floats2bfloat162_rn(v.x, v.y);
        __nv_bfloat162 p1 = __floats2bfloat162_rn(v.z, v.w);
        uint2 u;
        u.x = *(uint32_t*)&p0;
        u.y = *(uint32_t*)&p1;
        *(uint2*)(o + 4 * i) = u;
    } else {
        *(uint2*)(o + 700) = make_uint2(0u, 0u);       // pad 700..703
    }
}
__global__ void prep_w1(const float* __restrict__ W1) {
    const int h = blockIdx.x;
    const float* wr = W1 + (size_t)h * D_;
    __nv_bfloat16* o = g_w1 + (size_t)h * K1;
    for (int d = threadIdx.x; d < D_; d += 256)
        o[d] = __float2bfloat16(wr[d]);
    if (threadIdx.x < K1 - D_) o[D_ + threadIdx.x] = __float2bfloat16(0.f);
}
__global__ void prep_w2(const float* __restrict__ W2) {
    int i = blockIdx.x * blockDim.x + threadIdx.x;
    if (i < H_ * H_) g_w2[i] = __float2bfloat16(W2[i]);
}

// ---------------- GEMM: out[t*B+m][n] = bf16(A[t*B+m][:].Bm[n][:] + bias[n]) ----------
// grid (4 n-tiles, CH t), 256 threads; t = t0 + blockIdx.y. CTA tile 128x128, K=KK.
// 8 warps as 2(m)x4(n), each 64x32 via m16n8k16. K-stage 64 (SW128), 3-stage ring.
template <int KK>
__global__ __launch_bounds__(256, 2) void gemm_mma(const __nv_bfloat16* __restrict__ Asrc,
                                                   const __nv_bfloat16* __restrict__ Bsrc,
                                                   const float* __restrict__ bias,
                                                   __nv_bfloat16* __restrict__ outp,
                                                   int t0) {
    constexpr int NS = KK / 64;
    constexpr int KB2 = KK * 2;
    extern __shared__ __align__(128) char smem[];
    const int tid = threadIdx.x, lane = tid & 31, wid = tid >> 5;
    const int t = t0 + blockIdx.y, nbase = blockIdx.x * 128;
    const int wm = wid >> 2, wn = wid & 3;

    const char* gA = (const char*)Asrc + (size_t)t * B_ * KB2;
    const char* gB = (const char*)Bsrc + (size_t)nbase * KB2;
    const uint32_t sAu = smem_u32(smem);
    const uint32_t sBu = sAu + STG * SBUF;

    const int lrow = tid >> 1;
    const int lhalf = (tid & 1) * 64;
    const size_t grow = (size_t)lrow * KB2;

    const int arow = lane & 15;
    const int acol = (lane >> 4) * 16;
    const int brow = (lane & 7) + ((lane & 16) ? 8 : 0);
    const int bcol = (lane & 8) ? 16 : 0;

    float acc[4][4][4];
#pragma unroll
    for (int i = 0; i < 4; i++)
#pragma unroll
        for (int j = 0; j < 4; j++)
#pragma unroll
            for (int q = 0; q < 4; q++) acc[i][j][q] = 0.f;

#define LOADSTAGE(s, buf)                                                       \
    do {                                                                        \
        const char* ga = gA + grow + (s) * 128 + lhalf;                         \
        const char* gb = gB + grow + (s) * 128 + lhalf;                         \
        const uint32_t rb = (uint32_t)(lrow * 128 + lhalf);                     \
        _Pragma("unroll")                                                       \
        for (int j = 0; j < 4; j++) {                                           \
            uint32_t sw = sw128(rb + j * 16);                                   \
            cp16(sAu + (buf) * SBUF + sw, ga + j * 16);                         \
            cp16(sBu + (buf) * SBUF + sw, gb + j * 16);                         \
        }                                                                       \
    } while (0)

#pragma unroll
    for (int p = 0; p < STG - 1; p++) {
        LOADSTAGE(p, p);
        asm volatile("cp.async.commit_group;");
    }

    int buf = 0, nbuf = STG - 1;
    for (int s = 0; s < NS; s++) {
        asm volatile("cp.async.wait_group 1;");
        __syncthreads();
        if (s + STG - 1 < NS) LOADSTAGE(s + STG - 1, nbuf);
        asm volatile("cp.async.commit_group;");

        const uint32_t abase = sAu + buf * SBUF;
        const uint32_t bbase = sBu + buf * SBUF;
#pragma unroll
        for (int ks = 0; ks < 4; ks++) {
            uint32_t a[4][4], bf[4][2];
#pragma unroll
            for (int i = 0; i < 4; i++)
                ldsm4(a[i][0], a[i][1], a[i][2], a[i][3],
                      abase + sw128((wm * 64 + i * 16 + arow) * 128 + ks * 32 + acol));
#pragma unroll
            for (int j = 0; j < 2; j++)
                ldsm4(bf[2 * j][0], bf[2 * j][1], bf[2 * j + 1][0], bf[2 * j + 1][1],
                      bbase + sw128((wn * 32 + j * 16 + brow) * 128 + ks * 32 + bcol));
#pragma unroll
            for (int i = 0; i < 4; i++)
#pragma unroll
                for (int j = 0; j < 4; j++) mma16816(acc[i][j], a[i], bf[j]);
        }
        buf = (buf + 1 == STG) ? 0 : buf + 1;
        nbuf = (nbuf + 1 == STG) ? 0 : nbuf + 1;
    }
    __syncthreads();

    const int r0 = wm * 64 + (lane >> 2);
    const int cb = wn * 32 + (lane & 3) * 2;
#pragma unroll
    for (int j = 0; j < 4; j++) {
        const int col = nbase + cb + j * 8;
        const float2 bl = *(const float2*)(bias + col);
#pragma unroll
        for (int i = 0; i < 4; i++) {
            const int rb = r0 + i * 16;
            __nv_bfloat162 v0 = __floats2bfloat162_rn(acc[i][j][0] + bl.x,
                                                      acc[i][j][1] + bl.y);
            __nv_bfloat162 v1 = __floats2bfloat162_rn(acc[i][j][2] + bl.x,
                                                      acc[i][j][3] + bl.y);
            *(uint32_t*)(smem + rb * ERS + (cb + j * 8) * 2)       = *(uint32_t*)&v0;
            *(uint32_t*)(smem + (rb + 8) * ERS + (cb + j * 8) * 2) = *(uint32_t*)&v1;
        }
    }
    __syncthreads();
    char* gOut = (char*)outp + ((size_t)t * B_ * H_ + nbase) * 2;
#pragma unroll
    for (int c = tid; c < 2048; c += 256) {
        const int row = c >> 4, off = (c & 15) * 16;
        uint4 v = *(const uint4*)(smem + row * ERS + off);
        *(uint4*)(gOut + (size_t)row * (H_ * 2) + off) = v;
    }
}

// ---------------- scan1: LIF over cur1 chunk [t0, t0+CH), state in g_v1 ----------------
// grid (2 h-halves, 128 b), 128 threads; thread = one (b, h-pair). No barriers.
__global__ __launch_bounds__(128) void scan1_kernel(int t0) {
    const int q = blockIdx.x, b = blockIdx.y;
    const int tid = threadIdx.x;
    const size_t off2 = (size_t)b * (H_ / 2) + q * 128 + tid;   // bf162 index
    const __nv_bfloat162* cp = (const __nv_bfloat162*)g_cur + off2;
    __nv_bfloat162* sp = (__nv_bfloat162*)g_s1 + off2;
    const int stride = B_ * H_ / 2;
    float v0, v1;
    if (t0 == 0) { v0 = 0.f; v1 = 0.f; }
    else { float2 s = *(float2*)(g_v1 + 2 * off2); v0 = s.x; v1 = s.y; }
    for (int tl = 0; tl < CH; tl += 10) {
        __nv_bfloat162 I[10];
#pragma unroll
        for (int u = 0; u < 10; u++)
            I[u] = cp[(size_t)(t0 + tl + u) * stride];
#pragma unroll
        for (int u = 0; u < 10; u++) {
            float2 f = __bfloat1622float2(I[u]);
            v0 += (f.x - v0) * 0.5f;
            v1 += (f.y - v1) * 0.5f;
            bool s0 = (v0 >= 1.0f), s1v = (v1 >= 1.0f);
            sp[(size_t)(t0 + tl + u) * stride] =
                __floats2bfloat162_rn(s0 ? 1.f : 0.f, s1v ? 1.f : 0.f);
            if (s0) v0 = 0.f;
            if (s1v) v1 = 0.f;
        }
    }
    *(float2*)(g_v1 + 2 * off2) = make_float2(v0, v1);
}

// ---------------- scan2: LIF over cur2 chunk, running counts in g_S2, state g_v2 -------
__global__ __launch_bounds__(128) void scan2_kernel(int t0) {
    const int q = blockIdx.x, b = blockIdx.y;
    const int tid = threadIdx.x;
    const size_t off2 = (size_t)b * (H_ / 2) + q * 128 + tid;
    const __nv_bfloat162* cp = (const __nv_bfloat162*)g_cur + off2;
    const int stride = B_ * H_ / 2;
    float v0, v1, c0, c1;
    if (t0 == 0) { v0 = v1 = c0 = c1 = 0.f; }
    else {
        float2 s = *(float2*)(g_v2 + 2 * off2); v0 = s.x; v1 = s.y;
        float2 c = *(float2*)(g_S2 + 2 * off2); c0 = c.x; c1 = c.y;
    }
    for (int tl = 0; tl < CH; tl += 10) {
        __nv_bfloat162 I[10];
#pragma unroll
        for (int u = 0; u < 10; u++)
            I[u] = cp[(size_t)(t0 + tl + u) * stride];
#pragma unroll
        for (int u = 0; u < 10; u++) {
            float2 f = __bfloat1622float2(I[u]);
            v0 += (f.x - v0) * 0.5f;
            v1 += (f.y - v1) * 0.5f;
            if (v0 >= 1.0f) { v0 = 0.f; c0 += 1.f; }
            if (v1 >= 1.0f) { v1 = 0.f; c1 += 1.f; }
        }
    }
    *(float2*)(g_v2 + 2 * off2) = make_float2(v0, v1);
    *(float2*)(g_S2 + 2 * off2) = make_float2(c0, c1);
}

// ---------------- final: out[b,o] = 500*b3[o] + sum_h S2[b,h] * W3[o,h] ----------------
__global__ void final_kernel(const float* __restrict__ W3, const float* __restrict__ b3,
                             float* __restrict__ out) {
    __shared__ float sW3[O_ * H_];
    __shared__ float part[4 * O_];
    const int b = blockIdx.x, tid = threadIdx.x;
    for (int i = tid; i < O_ * H_; i += 128) sW3[i] = W3[i];
    __syncthreads();

    float acc[O_];
#pragma unroll
    for (int o = 0; o < O_; o++) acc[o] = 0.f;
    for (int h = tid; h < H_; h += 128) {
        float s2 = g_S2[b * H_ + h];
#pragma unroll
        for (int o = 0; o < O_; o++) acc[o] += s2 * sW3[o * H_ + h];
    }
#pragma unroll
    for (int off = 16; off; off >>= 1)
#pragma unroll
        for (int o = 0; o < O_; o++)
            acc[o] += __shfl_down_sync(0xffffffffu, acc[o], off);
    if ((tid & 31) == 0)
#pragma unroll
        for (int o = 0; o < O_; o++) part[(tid >> 5) * O_ + o] = acc[o];
    __syncthreads();
    if (tid < O_) {
        float r = 500.0f * b3[tid];
#pragma unroll
        for (int w = 0; w < 4; w++) r += part[w * O_ + tid];
        out[b * O_ + tid] = r;
    }
}

// ---------------- stream/event context (created once, on the un-captured call) ---------
struct PipeCtx {
    cudaStream_t s1, s2, s3;
    cudaEvent_t eRoot, eW, ePX[NCH], eG1[NCH], eS1[NCH], eG2[NCH], eFin;
    PipeCtx() {
        cudaStreamCreateWithFlags(&s1, cudaStreamNonBlocking);
        cudaStreamCreateWithFlags(&s2, cudaStreamNonBlocking);
        cudaStreamCreateWithFlags(&s3, cudaStreamNonBlocking);
        cudaEventCreateWithFlags(&eRoot, cudaEventDisableTiming);
        cudaEventCreateWithFlags(&eW, cudaEventDisableTiming);
        cudaEventCreateWithFlags(&eFin, cudaEventDisableTiming);
        for (int i = 0; i < NCH; i++) {
            cudaEventCreateWithFlags(&ePX[i], cudaEventDisableTiming);
            cudaEventCreateWithFlags(&eG1[i], cudaEventDisableTiming);
            cudaEventCreateWithFlags(&eS1[i], cudaEventDisableTiming);
            cudaEventCreateWithFlags(&eG2[i], cudaEventDisableTiming);
        }
    }
};

// ---------------- launch: capture-legal 4-stream software pipeline over 5 chunks -------
// s0 (origin): gemm1 chunks + final.  s1: prep_x + scan1 chain.
// s2: gemm2 chunks.                   s3: weight prep + scan2 chain.
extern "C" void kernel_launch(void* const* d_in, const int* in_sizes, int n_in,
                              void* d_out, int out_size) {
    const float* x  = (const float*)d_in[0];   // [128, 500, 700]
    const float* W1 = (const float*)d_in[1];   // [512, 700]
    const float* b1 = (const float*)d_in[2];   // [512]
    const float* W2 = (const float*)d_in[3];   // [512, 512]
    const float* b2 = (const float*)d_in[4];   // [512]
    const float* W3 = (const float*)d_in[5];   // [20, 512]
    const float* b3 = (const float*)d_in[6];   // [20]
    float* out = (float*)d_out;                // [128, 20]

    static PipeCtx P;                          // created on first (eager) call only
    const cudaStream_t s0 = 0;                 // capture-origin stream

    __nv_bfloat16* xc;   cudaGetSymbolAddress((void**)&xc,   g_xc);
    __nv_bfloat16* w1c;  cudaGetSymbolAddress((void**)&w1c,  g_w1);
    __nv_bfloat16* w2c;  cudaGetSymbolAddress((void**)&w2c,  g_w2);
    __nv_bfloat16* s1c;  cudaGetSymbolAddress((void**)&s1c,  g_s1);
    __nv_bfloat16* curc; cudaGetSymbolAddress((void**)&curc, g_cur);

    cudaFuncSetAttribute(gemm_mma<K1>, cudaFuncAttributeMaxDynamicSharedMemorySize, GSMEM);
    cudaFuncSetAttribute(gemm_mma<K2>, cudaFuncAttributeMaxDynamicSharedMemorySize, GSMEM);

    // ---- FORK: all side streams join the capture via an event recorded on s0 ----
    cudaEventRecord(P.eRoot, s0);
    cudaStreamWaitEvent(P.s1, P.eRoot, 0);
    cudaStreamWaitEvent(P.s2, P.eRoot, 0);
    cudaStreamWaitEvent(P.s3, P.eRoot, 0);

    // s3: weight prep (overlaps prep_x chunk 0 on s1)
    prep_w1<<<H_, 256, 0, P.s3>>>(W1);
    prep_w2<<<(H_ * H_ + 255) / 256, 256, 0, P.s3>>>(W2);
    cudaEventRecord(P.eW, P.s3);

    // s1: x chunks
    for (int c = 0; c < NCH; c++) {
        prep_x_chunk<<<8800, 256, 0, P.s1>>>(x, c * CH);
        cudaEventRecord(P.ePX[c], P.s1);
    }

    // s0: gemm1 chunks
    cudaStreamWaitEvent(s0, P.eW, 0);
    for (int c = 0; c < NCH; c++) {
        cudaStreamWaitEvent(s0, P.ePX[c], 0);
        gemm_mma<K1><<<dim3(4, CH), 256, GSMEM, s0>>>(xc, w1c, b1, curc, c * CH);
        cudaEventRecord(P.eG1[c], s0);
    }

    // s1: scan1 chunks (state chain via s1 stream order)
    for (int c = 0; c < NCH; c++) {
        cudaStreamWaitEvent(P.s1, P.eG1[c], 0);
        scan1_kernel<<<dim3(2, B_), 128, 0, P.s1>>>(c * CH);
        cudaEventRecord(P.eS1[c], P.s1);
    }

    // s2: gemm2 chunks (co-run with later gemm1 chunks, filling wave tails)
    cudaStreamWaitEvent(P.s2, P.eW, 0);
    for (int c = 0; c < NCH; c++) {
        cudaStreamWaitEvent(P.s2, P.eS1[c], 0);
        gemm_mma<K2><<<dim3(4, CH), 256, GSMEM, P.s2>>>(s1c, w2c, b2, curc, c * CH);
        cudaEventRecord(P.eG2[c], P.s2);
    }

    // s3: scan2 chunks (state chain via s3 stream order)
    for (int c = 0; c < NCH; c++) {
        cudaStreamWaitEvent(P.s3, P.eG2[c], 0);
        scan2_kernel<<<dim3(2, B_), 128, 0, P.s3>>>(c * CH);
    }
    cudaEventRecord(P.eFin, P.s3);

    // ---- JOIN: every forked stream merges back into s0 before capture ends ----
    cudaStreamWaitEvent(s0, P.eS1[NCH - 1], 0);   // joins s1
    cudaStreamWaitEvent(s0, P.eG2[NCH - 1], 0);   // joins s2
    cudaStreamWaitEvent(s0, P.eFin, 0);           // joins s3
    final_kernel<<<B_, 128, 0, s0>>>(W3, b3, out);
}